// round 2
// baseline (speedup 1.0000x reference)
#include <cuda_runtime.h>

#define BDIM   256
#define ROWS   8            // batch rows per CTA
#define NCTA   128          // 1024 / 8
#define LATD   512
#define HIDD   1024
#define IN_F   256
#define OUT_F  64
#define NSTEPS 20
#define SROW   10           // padded smem row stride in floats (keeps 8B pair alignment, 8-way not 32-way conflicts)

// ---- packed fp32 (f32x2) helpers: the only path to full-rate fp32 FMA on Blackwell ----
__device__ __forceinline__ unsigned long long pack2(float v) {
    unsigned long long r;
    asm("mov.b64 %0, {%1, %1};" : "=l"(r) : "r"(__float_as_uint(v)));
    return r;
}
__device__ __forceinline__ void ffma2(unsigned long long &d, unsigned long long a, unsigned long long b) {
    asm("fma.rn.f32x2 %0, %1, %2, %0;" : "+l"(d) : "l"(a), "l"(b));
}
__device__ __forceinline__ void unpack2(unsigned long long v, float &lo, float &hi) {
    unsigned int a, b;
    asm("mov.b64 {%0, %1}, %2;" : "=r"(a), "=r"(b) : "l"(v));
    lo = __uint_as_float(a);
    hi = __uint_as_float(b);
}
__device__ __forceinline__ float fast_tanh(float x) {
    float ax = fabsf(x);
    float e  = __expf(-2.0f * ax);
    float r  = __fdividef(1.0f - e, 1.0f + e);
    return copysignf(r, x);
}

// One CTA integrates 8 batch rows through the entire ODE. No inter-CTA deps.
// Shared state is stored transposed [k][row] so adjacent rows form f32x2 pairs.
extern "C" __global__ void __launch_bounds__(BDIM, 1)
ode_kernel(const float* __restrict__ x,     const float* __restrict__ W_in,
           const float* __restrict__ b_in,  const float* __restrict__ W1,
           const float* __restrict__ b1,    const float* __restrict__ W2,
           const float* __restrict__ b2,    const float* __restrict__ W_out,
           const float* __restrict__ b_out, float* __restrict__ out)
{
    extern __shared__ float sm[];
    float* h_t   = sm;                    // [LATD][SROW]  master h
    float* tmp_t = sm + LATD * SROW;      // [LATD][SROW]  stage input h + c*dt*k
    float* A_t   = sm + 2 * LATD * SROW;  // [HIDD][SROW]  tanh activations (also x staging)

    const int tid  = threadIdx.x;
    const int row0 = blockIdx.x * ROWS;
    const int n0   = tid * 4;   // GEMM1: 4 consecutive columns of HID
    const int j0   = tid * 2;   // GEMM2/init: 2 consecutive columns of LAT

    // persistent per-thread constants
    float b1v[4], w1t[4];
    #pragma unroll
    for (int c = 0; c < 4; c++) {
        b1v[c] = b1[n0 + c];
        w1t[c] = W1[(size_t)LATD * HIDD + n0 + c];   // t-column of W1 (row 512)
    }
    float b2v[2]  = { b2[j0],   b2[j0 + 1] };
    float binv[2] = { b_in[j0], b_in[j0 + 1] };

    // ---- stage x block into A_t transposed: xt[i][m] ----
    for (int idx = tid; idx < IN_F * ROWS; idx += BDIM) {
        int m = idx >> 8;       // idx / 256
        int i = idx & 255;
        A_t[i * SROW + m] = x[(size_t)(row0 + m) * IN_F + i];
    }
    __syncthreads();

    // ---- h0 = tanh(x @ W_in + b_in), K=256 ----
    {
        unsigned long long acc[4][2];
        #pragma unroll
        for (int p = 0; p < 4; p++) { acc[p][0] = 0ull; acc[p][1] = 0ull; }
        #pragma unroll 4
        for (int k = 0; k < IN_F; k++) {
            float2 w = *(const float2*)(W_in + (size_t)k * LATD + j0);
            unsigned long long wp0 = pack2(w.x), wp1 = pack2(w.y);
            #pragma unroll
            for (int p = 0; p < 4; p++) {
                unsigned long long a = *(const unsigned long long*)(A_t + k * SROW + 2 * p);
                ffma2(acc[p][0], a, wp0);
                ffma2(acc[p][1], a, wp1);
            }
        }
        #pragma unroll
        for (int p = 0; p < 4; p++)
            #pragma unroll
            for (int c = 0; c < 2; c++) {
                float lo, hi; unpack2(acc[p][c], lo, hi);
                float2 v;
                v.x = fast_tanh(lo + binv[c]);
                v.y = fast_tanh(hi + binv[c]);
                *(float2*)(h_t + (j0 + c) * SROW + 2 * p) = v;
            }
    }

    const float dt = (1.0f - 0.0f) / NSTEPS;   // 0.05
    float rk[4][2][2];                          // RK4 accumulator (k1+2k2+2k3+k4), in registers

    for (int step = 0; step < NSTEPS; step++) {
        float t = dt * step;
        #pragma unroll
        for (int stage = 0; stage < 4; stage++) {
            const float ts = t + ((stage == 0) ? 0.0f : (stage == 3) ? dt : 0.5f * dt);
            const float* src = (stage == 0) ? h_t : tmp_t;
            __syncthreads();   // src ready; A_t free to overwrite

            // ---- GEMM1: A = tanh(src @ W1 + b1 + ts * W1[512,:]) ----
            unsigned long long a1[4][4];
            #pragma unroll
            for (int p = 0; p < 4; p++)
                #pragma unroll
                for (int c = 0; c < 4; c++) a1[p][c] = 0ull;
            const float* w1p = W1 + n0;
            #pragma unroll 4
            for (int k = 0; k < LATD; k++) {
                float4 w = *(const float4*)(w1p + (size_t)k * HIDD);
                unsigned long long wp0 = pack2(w.x), wp1 = pack2(w.y);
                unsigned long long wp2 = pack2(w.z), wp3 = pack2(w.w);
                #pragma unroll
                for (int p = 0; p < 4; p++) {
                    unsigned long long a = *(const unsigned long long*)(src + k * SROW + 2 * p);
                    ffma2(a1[p][0], a, wp0);
                    ffma2(a1[p][1], a, wp1);
                    ffma2(a1[p][2], a, wp2);
                    ffma2(a1[p][3], a, wp3);
                }
            }
            #pragma unroll
            for (int c = 0; c < 4; c++) {
                float bb = b1v[c] + ts * w1t[c];
                #pragma unroll
                for (int p = 0; p < 4; p++) {
                    float lo, hi; unpack2(a1[p][c], lo, hi);
                    float2 v;
                    v.x = fast_tanh(lo + bb);
                    v.y = fast_tanh(hi + bb);
                    *(float2*)(A_t + (n0 + c) * SROW + 2 * p) = v;
                }
            }
            __syncthreads();   // A_t ready

            // ---- GEMM2: k = A @ W2 + b2, fused RK4 state update ----
            unsigned long long a2[4][2];
            #pragma unroll
            for (int p = 0; p < 4; p++) { a2[p][0] = 0ull; a2[p][1] = 0ull; }
            const float* w2p = W2 + j0;
            #pragma unroll 4
            for (int k = 0; k < HIDD; k++) {
                float2 w = *(const float2*)(w2p + (size_t)k * LATD);
                unsigned long long wp0 = pack2(w.x), wp1 = pack2(w.y);
                #pragma unroll
                for (int p = 0; p < 4; p++) {
                    unsigned long long a = *(const unsigned long long*)(A_t + k * SROW + 2 * p);
                    ffma2(a2[p][0], a, wp0);
                    ffma2(a2[p][1], a, wp1);
                }
            }
            #pragma unroll
            for (int c = 0; c < 2; c++) {
                #pragma unroll
                for (int p = 0; p < 4; p++) {
                    float klo, khi; unpack2(a2[p][c], klo, khi);
                    klo += b2v[c]; khi += b2v[c];
                    float* hp = h_t + (j0 + c) * SROW + 2 * p;
                    float2 hv = *(const float2*)hp;
                    if (stage == 0) {
                        rk[p][c][0] = klo; rk[p][c][1] = khi;
                        float2 tv; tv.x = hv.x + 0.5f * dt * klo; tv.y = hv.y + 0.5f * dt * khi;
                        *(float2*)(tmp_t + (j0 + c) * SROW + 2 * p) = tv;
                    } else if (stage == 1) {
                        rk[p][c][0] += 2.0f * klo; rk[p][c][1] += 2.0f * khi;
                        float2 tv; tv.x = hv.x + 0.5f * dt * klo; tv.y = hv.y + 0.5f * dt * khi;
                        *(float2*)(tmp_t + (j0 + c) * SROW + 2 * p) = tv;
                    } else if (stage == 2) {
                        rk[p][c][0] += 2.0f * klo; rk[p][c][1] += 2.0f * khi;
                        float2 tv; tv.x = hv.x + dt * klo; tv.y = hv.y + dt * khi;
                        *(float2*)(tmp_t + (j0 + c) * SROW + 2 * p) = tv;
                    } else {
                        rk[p][c][0] += klo; rk[p][c][1] += khi;
                        float2 nh;
                        nh.x = hv.x + (dt / 6.0f) * rk[p][c][0];
                        nh.y = hv.y + (dt / 6.0f) * rk[p][c][1];
                        *(float2*)hp = nh;
                    }
                }
            }
        }
    }
    __syncthreads();

    // ---- out = h[:, :256] @ W_out + b_out ----
    {
        const int m  = tid >> 5;          // 0..7
        const int o0 = (tid & 31) * 2;    // 0..62
        float s0 = 0.0f, s1 = 0.0f;
        #pragma unroll 4
        for (int k = 0; k < LATD / 2; k++) {
            float hv = h_t[k * SROW + m];
            float2 w = *(const float2*)(W_out + (size_t)k * OUT_F + o0);
            s0 = fmaf(hv, w.x, s0);
            s1 = fmaf(hv, w.y, s1);
        }
        float2 o;
        o.x = s0 + b_out[o0];
        o.y = s1 + b_out[o0 + 1];
        *(float2*)(out + (size_t)(row0 + m) * OUT_F + o0) = o;
    }
}

extern "C" void kernel_launch(void* const* d_in, const int* in_sizes, int n_in,
                              void* d_out, int out_size)
{
    const float* x     = (const float*)d_in[0];
    const float* W_in  = (const float*)d_in[1];
    const float* b_in  = (const float*)d_in[2];
    const float* W1    = (const float*)d_in[3];
    const float* b1    = (const float*)d_in[4];
    const float* W2    = (const float*)d_in[5];
    const float* b2    = (const float*)d_in[6];
    const float* W_out = (const float*)d_in[7];
    const float* b_out = (const float*)d_in[8];

    size_t smem = (size_t)(2 * LATD + HIDD) * SROW * sizeof(float);  // 80 KB

    static bool attr_done = false;
    if (!attr_done) {
        cudaFuncSetAttribute(ode_kernel, cudaFuncAttributeMaxDynamicSharedMemorySize, (int)smem);
        attr_done = true;
    }

    ode_kernel<<<NCTA, BDIM, smem>>>(x, W_in, b_in, W1, b1, W2, b2, W_out, b_out,
                                     (float*)d_out);
}

// round 3
// speedup vs baseline: 1.6085x; 1.6085x over previous
#include <cuda_runtime.h>

#define BDIM   512
#define ROWS   8            // batch rows per CTA
#define NCTA   128          // 1024 / 8
#define LATD   512
#define HIDD   1024
#define IN_F   256
#define OUT_F  64
#define NSTEPS 20
#define SROW   10           // padded smem row stride (8B pair alignment, 8-way not 32-way conflicts)

// ---- packed fp32 (f32x2) helpers ----
__device__ __forceinline__ unsigned long long pack2(float v) {
    unsigned long long r;
    asm("mov.b64 %0, {%1, %1};" : "=l"(r) : "r"(__float_as_uint(v)));
    return r;
}
__device__ __forceinline__ void ffma2(unsigned long long &d, unsigned long long a, unsigned long long b) {
    asm("fma.rn.f32x2 %0, %1, %2, %0;" : "+l"(d) : "l"(a), "l"(b));
}
__device__ __forceinline__ void unpack2(unsigned long long v, float &lo, float &hi) {
    unsigned int a, b;
    asm("mov.b64 {%0, %1}, %2;" : "=r"(a), "=r"(b) : "l"(v));
    lo = __uint_as_float(a);
    hi = __uint_as_float(b);
}
__device__ __forceinline__ float fast_tanh(float x) {
    float ax = fabsf(x);
    float e  = __expf(-2.0f * ax);
    float r  = __fdividef(1.0f - e, 1.0f + e);
    return copysignf(r, x);
}

// One CTA integrates 8 batch rows through the entire ODE. 512 threads:
// column-block ownership is shared by thread pairs (cid) that split the K
// range (kh = tid>>8). kh=1 writes raw partial sums into the destination
// smem buffer; kh=0 adds its half, applies the nonlinearity / RK4 update.
extern "C" __global__ void __launch_bounds__(BDIM, 1)
ode_kernel(const float* __restrict__ x,     const float* __restrict__ W_in,
           const float* __restrict__ b_in,  const float* __restrict__ W1,
           const float* __restrict__ b1,    const float* __restrict__ W2,
           const float* __restrict__ b2,    const float* __restrict__ W_out,
           const float* __restrict__ b_out, float* __restrict__ out)
{
    extern __shared__ float sm[];
    float* h_t   = sm;                    // [LATD][SROW]  master h (transposed)
    float* tmp_t = sm + LATD * SROW;      // [LATD][SROW]  stage input / GEMM2 partials
    float* A_t   = sm + 2 * LATD * SROW;  // [HIDD][SROW]  activations / GEMM1 partials / x staging

    const int tid  = threadIdx.x;
    const int cid  = tid & 255;           // column-block id (shared by kh pair)
    const int kh   = tid >> 8;            // K-half: 0 or 1
    const int row0 = blockIdx.x * ROWS;
    const int n0   = cid * 4;             // GEMM1: 4 consecutive HID columns
    const int j0   = cid * 2;             // GEMM2: 2 consecutive LAT columns

    // per-thread constants (finalize work happens on kh==0, but cheap to load on both)
    float b1v[4], w1t[4];
    #pragma unroll
    for (int c = 0; c < 4; c++) {
        b1v[c] = b1[n0 + c];
        w1t[c] = W1[(size_t)LATD * HIDD + n0 + c];   // t-row of W1 (row 512)
    }
    float b2v[2] = { b2[j0], b2[j0 + 1] };

    // ---- stage x block into A_t transposed: xt[i][m] ----
    for (int idx = tid; idx < IN_F * ROWS; idx += BDIM) {
        int m = idx >> 8;
        int i = idx & 255;
        A_t[i * SROW + m] = x[(size_t)(row0 + m) * IN_F + i];
    }
    __syncthreads();

    // ---- h0 = tanh(x @ W_in + b_in): 512 threads, 1 LAT column each, K=256 ----
    {
        const int j = tid;
        float bj = b_in[j];
        unsigned long long acc[4];
        #pragma unroll
        for (int p = 0; p < 4; p++) acc[p] = 0ull;
        #pragma unroll 4
        for (int k = 0; k < IN_F; k++) {
            unsigned long long wp = pack2(W_in[(size_t)k * LATD + j]);
            #pragma unroll
            for (int p = 0; p < 4; p++) {
                unsigned long long a = *(const unsigned long long*)(A_t + k * SROW + 2 * p);
                ffma2(acc[p], a, wp);
            }
        }
        #pragma unroll
        for (int p = 0; p < 4; p++) {
            float lo, hi; unpack2(acc[p], lo, hi);
            float2 v;
            v.x = fast_tanh(lo + bj);
            v.y = fast_tanh(hi + bj);
            *(float2*)(h_t + j * SROW + 2 * p) = v;
        }
    }

    const float dt = (1.0f - 0.0f) / NSTEPS;   // 0.05
    float rk[4][2][2];                          // RK4 accumulator (kh==0 threads only)

    for (int step = 0; step < NSTEPS; step++) {
        float t = dt * step;
        #pragma unroll
        for (int stage = 0; stage < 4; stage++) {
            const float ts = t + ((stage == 0) ? 0.0f : (stage == 3) ? dt : 0.5f * dt);
            const float* src = (stage == 0) ? h_t : tmp_t;
            __syncthreads();   // src ready; A_t free (previous GEMM2 consumed it)

            // ---- GEMM1 (K split): acc = src[K-half] @ W1[:, n0..n0+3] ----
            unsigned long long a1[4][4];
            #pragma unroll
            for (int p = 0; p < 4; p++)
                #pragma unroll
                for (int c = 0; c < 4; c++) a1[p][c] = 0ull;
            {
                const float* w1p = W1 + (size_t)(kh * (LATD / 2)) * HIDD + n0;
                const float* sp  = src + (kh * (LATD / 2)) * SROW;
                #pragma unroll 4
                for (int k = 0; k < LATD / 2; k++) {
                    float4 w = *(const float4*)(w1p + (size_t)k * HIDD);
                    unsigned long long wp0 = pack2(w.x), wp1 = pack2(w.y);
                    unsigned long long wp2 = pack2(w.z), wp3 = pack2(w.w);
                    #pragma unroll
                    for (int p = 0; p < 4; p++) {
                        unsigned long long a = *(const unsigned long long*)(sp + k * SROW + 2 * p);
                        ffma2(a1[p][0], a, wp0);
                        ffma2(a1[p][1], a, wp1);
                        ffma2(a1[p][2], a, wp2);
                        ffma2(a1[p][3], a, wp3);
                    }
                }
            }
            // kh=1 publishes raw partials into A_t
            if (kh) {
                #pragma unroll
                for (int c = 0; c < 4; c++)
                    #pragma unroll
                    for (int p = 0; p < 4; p++) {
                        float lo, hi; unpack2(a1[p][c], lo, hi);
                        float2 v; v.x = lo; v.y = hi;
                        *(float2*)(A_t + (n0 + c) * SROW + 2 * p) = v;
                    }
            }
            __syncthreads();   // partials visible
            if (!kh) {
                #pragma unroll
                for (int c = 0; c < 4; c++) {
                    float bb = b1v[c] + ts * w1t[c];
                    #pragma unroll
                    for (int p = 0; p < 4; p++) {
                        float lo, hi; unpack2(a1[p][c], lo, hi);
                        float2 pr = *(const float2*)(A_t + (n0 + c) * SROW + 2 * p);
                        float2 v;
                        v.x = fast_tanh(lo + pr.x + bb);
                        v.y = fast_tanh(hi + pr.y + bb);
                        *(float2*)(A_t + (n0 + c) * SROW + 2 * p) = v;
                    }
                }
            }
            __syncthreads();   // A_t (tanh activations) ready

            // ---- GEMM2 (K split): k = A[K-half] @ W2[:, j0..j0+1] ----
            unsigned long long a2[4][2];
            #pragma unroll
            for (int p = 0; p < 4; p++) { a2[p][0] = 0ull; a2[p][1] = 0ull; }
            {
                const float* w2p = W2 + (size_t)(kh * (HIDD / 2)) * LATD + j0;
                const float* ap  = A_t + (kh * (HIDD / 2)) * SROW;
                #pragma unroll 4
                for (int k = 0; k < HIDD / 2; k++) {
                    float2 w = *(const float2*)(w2p + (size_t)k * LATD);
                    unsigned long long wp0 = pack2(w.x), wp1 = pack2(w.y);
                    #pragma unroll
                    for (int p = 0; p < 4; p++) {
                        unsigned long long a = *(const unsigned long long*)(ap + k * SROW + 2 * p);
                        ffma2(a2[p][0], a, wp0);
                        ffma2(a2[p][1], a, wp1);
                    }
                }
            }
            // kh=1 publishes raw partials into tmp_t (free at this point)
            if (kh) {
                #pragma unroll
                for (int c = 0; c < 2; c++)
                    #pragma unroll
                    for (int p = 0; p < 4; p++) {
                        float lo, hi; unpack2(a2[p][c], lo, hi);
                        float2 v; v.x = lo; v.y = hi;
                        *(float2*)(tmp_t + (j0 + c) * SROW + 2 * p) = v;
                    }
            }
            __syncthreads();   // partials visible
            if (!kh) {
                #pragma unroll
                for (int c = 0; c < 2; c++) {
                    #pragma unroll
                    for (int p = 0; p < 4; p++) {
                        float lo, hi; unpack2(a2[p][c], lo, hi);
                        float2 pr = *(const float2*)(tmp_t + (j0 + c) * SROW + 2 * p);
                        float klo = lo + pr.x + b2v[c];
                        float khi = hi + pr.y + b2v[c];
                        float* hp = h_t + (j0 + c) * SROW + 2 * p;
                        float2 hv = *(const float2*)hp;
                        if (stage == 0) {
                            rk[p][c][0] = klo; rk[p][c][1] = khi;
                            float2 tv; tv.x = hv.x + 0.5f * dt * klo; tv.y = hv.y + 0.5f * dt * khi;
                            *(float2*)(tmp_t + (j0 + c) * SROW + 2 * p) = tv;
                        } else if (stage == 1) {
                            rk[p][c][0] += 2.0f * klo; rk[p][c][1] += 2.0f * khi;
                            float2 tv; tv.x = hv.x + 0.5f * dt * klo; tv.y = hv.y + 0.5f * dt * khi;
                            *(float2*)(tmp_t + (j0 + c) * SROW + 2 * p) = tv;
                        } else if (stage == 2) {
                            rk[p][c][0] += 2.0f * klo; rk[p][c][1] += 2.0f * khi;
                            float2 tv; tv.x = hv.x + dt * klo; tv.y = hv.y + dt * khi;
                            *(float2*)(tmp_t + (j0 + c) * SROW + 2 * p) = tv;
                        } else {
                            rk[p][c][0] += klo; rk[p][c][1] += khi;
                            float2 nh;
                            nh.x = hv.x + (dt / 6.0f) * rk[p][c][0];
                            nh.y = hv.y + (dt / 6.0f) * rk[p][c][1];
                            *(float2*)hp = nh;
                        }
                    }
                }
            }
        }
    }
    __syncthreads();

    // ---- out = h[:, :256] @ W_out + b_out : 512 threads, 1 output element each ----
    {
        const int m  = tid >> 6;          // 0..7
        const int o  = tid & 63;          // 0..63
        float s = 0.0f;
        #pragma unroll 4
        for (int k = 0; k < LATD / 2; k++) {
            s = fmaf(h_t[k * SROW + m], W_out[(size_t)k * OUT_F + o], s);
        }
        out[(size_t)(row0 + m) * OUT_F + o] = s + b_out[o];
    }
}

extern "C" void kernel_launch(void* const* d_in, const int* in_sizes, int n_in,
                              void* d_out, int out_size)
{
    const float* x     = (const float*)d_in[0];
    const float* W_in  = (const float*)d_in[1];
    const float* b_in  = (const float*)d_in[2];
    const float* W1    = (const float*)d_in[3];
    const float* b1    = (const float*)d_in[4];
    const float* W2    = (const float*)d_in[5];
    const float* b2    = (const float*)d_in[6];
    const float* W_out = (const float*)d_in[7];
    const float* b_out = (const float*)d_in[8];

    size_t smem = (size_t)(2 * LATD + HIDD) * SROW * sizeof(float);  // 80 KB

    static bool attr_done = false;
    if (!attr_done) {
        cudaFuncSetAttribute(ode_kernel, cudaFuncAttributeMaxDynamicSharedMemorySize, (int)smem);
        attr_done = true;
    }

    ode_kernel<<<NCTA, BDIM, smem>>>(x, W_in, b_in, W1, b1, W2, b2, W_out, b_out,
                                     (float*)d_out);
}

// round 4
// speedup vs baseline: 1.6121x; 1.0022x over previous
#include <cuda_runtime.h>

#define BDIM   512
#define ROWS   8            // batch rows per CTA
#define NCTA   128          // 1024 / 8
#define LATD   512
#define HIDD   1024
#define IN_F   256
#define OUT_F  64
#define NSTEPS 20
#define SROW   10           // padded smem row stride (8B pair alignment, 8-way not 32-way conflicts)

// ---- packed fp32 (f32x2) helpers ----
__device__ __forceinline__ unsigned long long pack2(float v) {
    unsigned long long r;
    asm("mov.b64 %0, {%1, %1};" : "=l"(r) : "r"(__float_as_uint(v)));
    return r;
}
__device__ __forceinline__ void ffma2(unsigned long long &d, unsigned long long a, unsigned long long b) {
    asm("fma.rn.f32x2 %0, %1, %2, %0;" : "+l"(d) : "l"(a), "l"(b));
}
__device__ __forceinline__ void unpack2(unsigned long long v, float &lo, float &hi) {
    unsigned int a, b;
    asm("mov.b64 {%0, %1}, %2;" : "=r"(a), "=r"(b) : "l"(v));
    lo = __uint_as_float(a);
    hi = __uint_as_float(b);
}
__device__ __forceinline__ float fast_tanh(float x) {
    float ax = fabsf(x);
    float e  = __expf(-2.0f * ax);
    float r  = __fdividef(1.0f - e, 1.0f + e);
    return copysignf(r, x);
}

// One CTA integrates 8 batch rows through the entire ODE. 512 threads:
// column-block ownership is shared by thread pairs (cid) that split the K
// range (kh = tid>>8). kh=1 writes raw partial sums into the destination
// smem buffer; kh=0 adds its half, applies the nonlinearity / RK4 update.
extern "C" __global__ void __launch_bounds__(BDIM, 1)
ode_kernel(const float* __restrict__ x,     const float* __restrict__ W_in,
           const float* __restrict__ b_in,  const float* __restrict__ W1,
           const float* __restrict__ b1,    const float* __restrict__ W2,
           const float* __restrict__ b2,    const float* __restrict__ W_out,
           const float* __restrict__ b_out, float* __restrict__ out)
{
    extern __shared__ float sm[];
    float* h_t   = sm;                    // [LATD][SROW]  master h (transposed)
    float* tmp_t = sm + LATD * SROW;      // [LATD][SROW]  stage input / GEMM2 partials
    float* A_t   = sm + 2 * LATD * SROW;  // [HIDD][SROW]  activations / GEMM1 partials / x staging

    const int tid  = threadIdx.x;
    const int cid  = tid & 255;           // column-block id (shared by kh pair)
    const int kh   = tid >> 8;            // K-half: 0 or 1
    const int row0 = blockIdx.x * ROWS;
    const int n0   = cid * 4;             // GEMM1: 4 consecutive HID columns
    const int j0   = cid * 2;             // GEMM2: 2 consecutive LAT columns

    // per-thread constants (finalize work happens on kh==0, but cheap to load on both)
    float b1v[4], w1t[4];
    #pragma unroll
    for (int c = 0; c < 4; c++) {
        b1v[c] = b1[n0 + c];
        w1t[c] = W1[(size_t)LATD * HIDD + n0 + c];   // t-row of W1 (row 512)
    }
    float b2v[2] = { b2[j0], b2[j0 + 1] };

    // ---- stage x block into A_t transposed: xt[i][m] ----
    for (int idx = tid; idx < IN_F * ROWS; idx += BDIM) {
        int m = idx >> 8;
        int i = idx & 255;
        A_t[i * SROW + m] = x[(size_t)(row0 + m) * IN_F + i];
    }
    __syncthreads();

    // ---- h0 = tanh(x @ W_in + b_in): 512 threads, 1 LAT column each, K=256 ----
    {
        const int j = tid;
        float bj = b_in[j];
        unsigned long long acc[4];
        #pragma unroll
        for (int p = 0; p < 4; p++) acc[p] = 0ull;
        #pragma unroll 4
        for (int k = 0; k < IN_F; k++) {
            unsigned long long wp = pack2(W_in[(size_t)k * LATD + j]);
            #pragma unroll
            for (int p = 0; p < 4; p++) {
                unsigned long long a = *(const unsigned long long*)(A_t + k * SROW + 2 * p);
                ffma2(acc[p], a, wp);
            }
        }
        #pragma unroll
        for (int p = 0; p < 4; p++) {
            float lo, hi; unpack2(acc[p], lo, hi);
            float2 v;
            v.x = fast_tanh(lo + bj);
            v.y = fast_tanh(hi + bj);
            *(float2*)(h_t + j * SROW + 2 * p) = v;
        }
    }

    const float dt = (1.0f - 0.0f) / NSTEPS;   // 0.05
    float rk[4][2][2];                          // RK4 accumulator (kh==0 threads only)

    for (int step = 0; step < NSTEPS; step++) {
        float t = dt * step;
        #pragma unroll
        for (int stage = 0; stage < 4; stage++) {
            const float ts = t + ((stage == 0) ? 0.0f : (stage == 3) ? dt : 0.5f * dt);
            const float* src = (stage == 0) ? h_t : tmp_t;
            __syncthreads();   // src ready; A_t free (previous GEMM2 consumed it)

            // ---- GEMM1 (K split): acc = src[K-half] @ W1[:, n0..n0+3] ----
            unsigned long long a1[4][4];
            #pragma unroll
            for (int p = 0; p < 4; p++)
                #pragma unroll
                for (int c = 0; c < 4; c++) a1[p][c] = 0ull;
            {
                const float* w1p = W1 + (size_t)(kh * (LATD / 2)) * HIDD + n0;
                const float* sp  = src + (kh * (LATD / 2)) * SROW;
                #pragma unroll 4
                for (int k = 0; k < LATD / 2; k++) {
                    float4 w = *(const float4*)(w1p + (size_t)k * HIDD);
                    unsigned long long wp0 = pack2(w.x), wp1 = pack2(w.y);
                    unsigned long long wp2 = pack2(w.z), wp3 = pack2(w.w);
                    #pragma unroll
                    for (int p = 0; p < 4; p++) {
                        unsigned long long a = *(const unsigned long long*)(sp + k * SROW + 2 * p);
                        ffma2(a1[p][0], a, wp0);
                        ffma2(a1[p][1], a, wp1);
                        ffma2(a1[p][2], a, wp2);
                        ffma2(a1[p][3], a, wp3);
                    }
                }
            }
            // kh=1 publishes raw partials into A_t
            if (kh) {
                #pragma unroll
                for (int c = 0; c < 4; c++)
                    #pragma unroll
                    for (int p = 0; p < 4; p++) {
                        float lo, hi; unpack2(a1[p][c], lo, hi);
                        float2 v; v.x = lo; v.y = hi;
                        *(float2*)(A_t + (n0 + c) * SROW + 2 * p) = v;
                    }
            }
            __syncthreads();   // partials visible
            if (!kh) {
                #pragma unroll
                for (int c = 0; c < 4; c++) {
                    float bb = b1v[c] + ts * w1t[c];
                    #pragma unroll
                    for (int p = 0; p < 4; p++) {
                        float lo, hi; unpack2(a1[p][c], lo, hi);
                        float2 pr = *(const float2*)(A_t + (n0 + c) * SROW + 2 * p);
                        float2 v;
                        v.x = fast_tanh(lo + pr.x + bb);
                        v.y = fast_tanh(hi + pr.y + bb);
                        *(float2*)(A_t + (n0 + c) * SROW + 2 * p) = v;
                    }
                }
            }
            __syncthreads();   // A_t (tanh activations) ready

            // ---- GEMM2 (K split): k = A[K-half] @ W2[:, j0..j0+1] ----
            unsigned long long a2[4][2];
            #pragma unroll
            for (int p = 0; p < 4; p++) { a2[p][0] = 0ull; a2[p][1] = 0ull; }
            {
                const float* w2p = W2 + (size_t)(kh * (HIDD / 2)) * LATD + j0;
                const float* ap  = A_t + (kh * (HIDD / 2)) * SROW;
                #pragma unroll 4
                for (int k = 0; k < HIDD / 2; k++) {
                    float2 w = *(const float2*)(w2p + (size_t)k * LATD);
                    unsigned long long wp0 = pack2(w.x), wp1 = pack2(w.y);
                    #pragma unroll
                    for (int p = 0; p < 4; p++) {
                        unsigned long long a = *(const unsigned long long*)(ap + k * SROW + 2 * p);
                        ffma2(a2[p][0], a, wp0);
                        ffma2(a2[p][1], a, wp1);
                    }
                }
            }
            // kh=1 publishes raw partials into tmp_t (free at this point)
            if (kh) {
                #pragma unroll
                for (int c = 0; c < 2; c++)
                    #pragma unroll
                    for (int p = 0; p < 4; p++) {
                        float lo, hi; unpack2(a2[p][c], lo, hi);
                        float2 v; v.x = lo; v.y = hi;
                        *(float2*)(tmp_t + (j0 + c) * SROW + 2 * p) = v;
                    }
            }
            __syncthreads();   // partials visible
            if (!kh) {
                #pragma unroll
                for (int c = 0; c < 2; c++) {
                    #pragma unroll
                    for (int p = 0; p < 4; p++) {
                        float lo, hi; unpack2(a2[p][c], lo, hi);
                        float2 pr = *(const float2*)(tmp_t + (j0 + c) * SROW + 2 * p);
                        float klo = lo + pr.x + b2v[c];
                        float khi = hi + pr.y + b2v[c];
                        float* hp = h_t + (j0 + c) * SROW + 2 * p;
                        float2 hv = *(const float2*)hp;
                        if (stage == 0) {
                            rk[p][c][0] = klo; rk[p][c][1] = khi;
                            float2 tv; tv.x = hv.x + 0.5f * dt * klo; tv.y = hv.y + 0.5f * dt * khi;
                            *(float2*)(tmp_t + (j0 + c) * SROW + 2 * p) = tv;
                        } else if (stage == 1) {
                            rk[p][c][0] += 2.0f * klo; rk[p][c][1] += 2.0f * khi;
                            float2 tv; tv.x = hv.x + 0.5f * dt * klo; tv.y = hv.y + 0.5f * dt * khi;
                            *(float2*)(tmp_t + (j0 + c) * SROW + 2 * p) = tv;
                        } else if (stage == 2) {
                            rk[p][c][0] += 2.0f * klo; rk[p][c][1] += 2.0f * khi;
                            float2 tv; tv.x = hv.x + dt * klo; tv.y = hv.y + dt * khi;
                            *(float2*)(tmp_t + (j0 + c) * SROW + 2 * p) = tv;
                        } else {
                            rk[p][c][0] += klo; rk[p][c][1] += khi;
                            float2 nh;
                            nh.x = hv.x + (dt / 6.0f) * rk[p][c][0];
                            nh.y = hv.y + (dt / 6.0f) * rk[p][c][1];
                            *(float2*)hp = nh;
                        }
                    }
                }
            }
        }
    }
    __syncthreads();

    // ---- out = h[:, :256] @ W_out + b_out : 512 threads, 1 output element each ----
    {
        const int m  = tid >> 6;          // 0..7
        const int o  = tid & 63;          // 0..63
        float s = 0.0f;
        #pragma unroll 4
        for (int k = 0; k < LATD / 2; k++) {
            s = fmaf(h_t[k * SROW + m], W_out[(size_t)k * OUT_F + o], s);
        }
        out[(size_t)(row0 + m) * OUT_F + o] = s + b_out[o];
    }
}

extern "C" void kernel_launch(void* const* d_in, const int* in_sizes, int n_in,
                              void* d_out, int out_size)
{
    const float* x     = (const float*)d_in[0];
    const float* W_in  = (const float*)d_in[1];
    const float* b_in  = (const float*)d_in[2];
    const float* W1    = (const float*)d_in[3];
    const float* b1    = (const float*)d_in[4];
    const float* W2    = (const float*)d_in[5];
    const float* b2    = (const float*)d_in[6];
    const float* W_out = (const float*)d_in[7];
    const float* b_out = (const float*)d_in[8];

    size_t smem = (size_t)(2 * LATD + HIDD) * SROW * sizeof(float);  // 80 KB

    static bool attr_done = false;
    if (!attr_done) {
        cudaFuncSetAttribute(ode_kernel, cudaFuncAttributeMaxDynamicSharedMemorySize, (int)smem);
        attr_done = true;
    }

    ode_kernel<<<NCTA, BDIM, smem>>>(x, W_in, b_in, W1, b1, W2, b2, W_out, b_out,
                                     (float*)d_out);
}

// round 5
// speedup vs baseline: 1.6158x; 1.0023x over previous
#include <cuda_runtime.h>

#define BDIM   512
#define ROWS   8            // batch rows per CTA
#define NCTA   128          // 1024 / 8
#define LATD   512
#define HIDD   1024
#define IN_F   256
#define OUT_F  64
#define NSTEPS 20
#define SROW   10           // padded smem row stride (8B pair alignment, 8-way not 32-way conflicts)

// ---- packed fp32 (f32x2) helpers ----
__device__ __forceinline__ unsigned long long pack2(float v) {
    unsigned long long r;
    asm("mov.b64 %0, {%1, %1};" : "=l"(r) : "r"(__float_as_uint(v)));
    return r;
}
__device__ __forceinline__ void ffma2(unsigned long long &d, unsigned long long a, unsigned long long b) {
    asm("fma.rn.f32x2 %0, %1, %2, %0;" : "+l"(d) : "l"(a), "l"(b));
}
__device__ __forceinline__ void unpack2(unsigned long long v, float &lo, float &hi) {
    unsigned int a, b;
    asm("mov.b64 {%0, %1}, %2;" : "=r"(a), "=r"(b) : "l"(v));
    lo = __uint_as_float(a);
    hi = __uint_as_float(b);
}
__device__ __forceinline__ float fast_tanh(float x) {
    float ax = fabsf(x);
    float e  = __expf(-2.0f * ax);
    float r  = __fdividef(1.0f - e, 1.0f + e);
    return copysignf(r, x);
}

// One CTA integrates 8 batch rows through the entire ODE. 512 threads:
// column-block ownership is shared by thread pairs (cid) that split the K
// range (kh = tid>>8). kh=1 writes raw partial sums into the destination
// smem buffer; kh=0 adds its half, applies the nonlinearity / RK4 update.
extern "C" __global__ void __launch_bounds__(BDIM, 1)
ode_kernel(const float* __restrict__ x,     const float* __restrict__ W_in,
           const float* __restrict__ b_in,  const float* __restrict__ W1,
           const float* __restrict__ b1,    const float* __restrict__ W2,
           const float* __restrict__ b2,    const float* __restrict__ W_out,
           const float* __restrict__ b_out, float* __restrict__ out)
{
    extern __shared__ float sm[];
    float* h_t   = sm;                    // [LATD][SROW]  master h (transposed)
    float* tmp_t = sm + LATD * SROW;      // [LATD][SROW]  stage input / GEMM2 partials
    float* A_t   = sm + 2 * LATD * SROW;  // [HIDD][SROW]  activations / GEMM1 partials / x staging

    const int tid  = threadIdx.x;
    const int cid  = tid & 255;           // column-block id (shared by kh pair)
    const int kh   = tid >> 8;            // K-half: 0 or 1
    const int row0 = blockIdx.x * ROWS;
    const int n0   = cid * 4;             // GEMM1: 4 consecutive HID columns
    const int j0   = cid * 2;             // GEMM2: 2 consecutive LAT columns

    // per-thread constants (finalize work happens on kh==0, but cheap to load on both)
    float b1v[4], w1t[4];
    #pragma unroll
    for (int c = 0; c < 4; c++) {
        b1v[c] = b1[n0 + c];
        w1t[c] = W1[(size_t)LATD * HIDD + n0 + c];   // t-row of W1 (row 512)
    }
    float b2v[2] = { b2[j0], b2[j0 + 1] };

    // ---- stage x block into A_t transposed: xt[i][m] ----
    for (int idx = tid; idx < IN_F * ROWS; idx += BDIM) {
        int m = idx >> 8;
        int i = idx & 255;
        A_t[i * SROW + m] = x[(size_t)(row0 + m) * IN_F + i];
    }
    __syncthreads();

    // ---- h0 = tanh(x @ W_in + b_in): 512 threads, 1 LAT column each, K=256 ----
    {
        const int j = tid;
        float bj = b_in[j];
        unsigned long long acc[4];
        #pragma unroll
        for (int p = 0; p < 4; p++) acc[p] = 0ull;
        #pragma unroll 4
        for (int k = 0; k < IN_F; k++) {
            unsigned long long wp = pack2(W_in[(size_t)k * LATD + j]);
            #pragma unroll
            for (int p = 0; p < 4; p++) {
                unsigned long long a = *(const unsigned long long*)(A_t + k * SROW + 2 * p);
                ffma2(acc[p], a, wp);
            }
        }
        #pragma unroll
        for (int p = 0; p < 4; p++) {
            float lo, hi; unpack2(acc[p], lo, hi);
            float2 v;
            v.x = fast_tanh(lo + bj);
            v.y = fast_tanh(hi + bj);
            *(float2*)(h_t + j * SROW + 2 * p) = v;
        }
    }

    const float dt = (1.0f - 0.0f) / NSTEPS;   // 0.05
    float rk[4][2][2];                          // RK4 accumulator (kh==0 threads only)

    for (int step = 0; step < NSTEPS; step++) {
        float t = dt * step;
        #pragma unroll
        for (int stage = 0; stage < 4; stage++) {
            const float ts = t + ((stage == 0) ? 0.0f : (stage == 3) ? dt : 0.5f * dt);
            const float* src = (stage == 0) ? h_t : tmp_t;
            __syncthreads();   // src ready; A_t free (previous GEMM2 consumed it)

            // ---- GEMM1 (K split): acc = src[K-half] @ W1[:, n0..n0+3] ----
            unsigned long long a1[4][4];
            #pragma unroll
            for (int p = 0; p < 4; p++)
                #pragma unroll
                for (int c = 0; c < 4; c++) a1[p][c] = 0ull;
            {
                const float* w1p = W1 + (size_t)(kh * (LATD / 2)) * HIDD + n0;
                const float* sp  = src + (kh * (LATD / 2)) * SROW;
                #pragma unroll 4
                for (int k = 0; k < LATD / 2; k++) {
                    float4 w = *(const float4*)(w1p + (size_t)k * HIDD);
                    unsigned long long wp0 = pack2(w.x), wp1 = pack2(w.y);
                    unsigned long long wp2 = pack2(w.z), wp3 = pack2(w.w);
                    #pragma unroll
                    for (int p = 0; p < 4; p++) {
                        unsigned long long a = *(const unsigned long long*)(sp + k * SROW + 2 * p);
                        ffma2(a1[p][0], a, wp0);
                        ffma2(a1[p][1], a, wp1);
                        ffma2(a1[p][2], a, wp2);
                        ffma2(a1[p][3], a, wp3);
                    }
                }
            }
            // kh=1 publishes raw partials into A_t
            if (kh) {
                #pragma unroll
                for (int c = 0; c < 4; c++)
                    #pragma unroll
                    for (int p = 0; p < 4; p++) {
                        float lo, hi; unpack2(a1[p][c], lo, hi);
                        float2 v; v.x = lo; v.y = hi;
                        *(float2*)(A_t + (n0 + c) * SROW + 2 * p) = v;
                    }
            }
            __syncthreads();   // partials visible
            if (!kh) {
                #pragma unroll
                for (int c = 0; c < 4; c++) {
                    float bb = b1v[c] + ts * w1t[c];
                    #pragma unroll
                    for (int p = 0; p < 4; p++) {
                        float lo, hi; unpack2(a1[p][c], lo, hi);
                        float2 pr = *(const float2*)(A_t + (n0 + c) * SROW + 2 * p);
                        float2 v;
                        v.x = fast_tanh(lo + pr.x + bb);
                        v.y = fast_tanh(hi + pr.y + bb);
                        *(float2*)(A_t + (n0 + c) * SROW + 2 * p) = v;
                    }
                }
            }
            __syncthreads();   // A_t (tanh activations) ready

            // ---- GEMM2 (K split): k = A[K-half] @ W2[:, j0..j0+1] ----
            unsigned long long a2[4][2];
            #pragma unroll
            for (int p = 0; p < 4; p++) { a2[p][0] = 0ull; a2[p][1] = 0ull; }
            {
                const float* w2p = W2 + (size_t)(kh * (HIDD / 2)) * LATD + j0;
                const float* ap  = A_t + (kh * (HIDD / 2)) * SROW;
                #pragma unroll 4
                for (int k = 0; k < HIDD / 2; k++) {
                    float2 w = *(const float2*)(w2p + (size_t)k * LATD);
                    unsigned long long wp0 = pack2(w.x), wp1 = pack2(w.y);
                    #pragma unroll
                    for (int p = 0; p < 4; p++) {
                        unsigned long long a = *(const unsigned long long*)(ap + k * SROW + 2 * p);
                        ffma2(a2[p][0], a, wp0);
                        ffma2(a2[p][1], a, wp1);
                    }
                }
            }
            // kh=1 publishes raw partials into tmp_t (free at this point)
            if (kh) {
                #pragma unroll
                for (int c = 0; c < 2; c++)
                    #pragma unroll
                    for (int p = 0; p < 4; p++) {
                        float lo, hi; unpack2(a2[p][c], lo, hi);
                        float2 v; v.x = lo; v.y = hi;
                        *(float2*)(tmp_t + (j0 + c) * SROW + 2 * p) = v;
                    }
            }
            __syncthreads();   // partials visible
            if (!kh) {
                #pragma unroll
                for (int c = 0; c < 2; c++) {
                    #pragma unroll
                    for (int p = 0; p < 4; p++) {
                        float lo, hi; unpack2(a2[p][c], lo, hi);
                        float2 pr = *(const float2*)(tmp_t + (j0 + c) * SROW + 2 * p);
                        float klo = lo + pr.x + b2v[c];
                        float khi = hi + pr.y + b2v[c];
                        float* hp = h_t + (j0 + c) * SROW + 2 * p;
                        float2 hv = *(const float2*)hp;
                        if (stage == 0) {
                            rk[p][c][0] = klo; rk[p][c][1] = khi;
                            float2 tv; tv.x = hv.x + 0.5f * dt * klo; tv.y = hv.y + 0.5f * dt * khi;
                            *(float2*)(tmp_t + (j0 + c) * SROW + 2 * p) = tv;
                        } else if (stage == 1) {
                            rk[p][c][0] += 2.0f * klo; rk[p][c][1] += 2.0f * khi;
                            float2 tv; tv.x = hv.x + 0.5f * dt * klo; tv.y = hv.y + 0.5f * dt * khi;
                            *(float2*)(tmp_t + (j0 + c) * SROW + 2 * p) = tv;
                        } else if (stage == 2) {
                            rk[p][c][0] += 2.0f * klo; rk[p][c][1] += 2.0f * khi;
                            float2 tv; tv.x = hv.x + dt * klo; tv.y = hv.y + dt * khi;
                            *(float2*)(tmp_t + (j0 + c) * SROW + 2 * p) = tv;
                        } else {
                            rk[p][c][0] += klo; rk[p][c][1] += khi;
                            float2 nh;
                            nh.x = hv.x + (dt / 6.0f) * rk[p][c][0];
                            nh.y = hv.y + (dt / 6.0f) * rk[p][c][1];
                            *(float2*)hp = nh;
                        }
                    }
                }
            }
        }
    }
    __syncthreads();

    // ---- out = h[:, :256] @ W_out + b_out : 512 threads, 1 output element each ----
    {
        const int m  = tid >> 6;          // 0..7
        const int o  = tid & 63;          // 0..63
        float s = 0.0f;
        #pragma unroll 4
        for (int k = 0; k < LATD / 2; k++) {
            s = fmaf(h_t[k * SROW + m], W_out[(size_t)k * OUT_F + o], s);
        }
        out[(size_t)(row0 + m) * OUT_F + o] = s + b_out[o];
    }
}

extern "C" void kernel_launch(void* const* d_in, const int* in_sizes, int n_in,
                              void* d_out, int out_size)
{
    const float* x     = (const float*)d_in[0];
    const float* W_in  = (const float*)d_in[1];
    const float* b_in  = (const float*)d_in[2];
    const float* W1    = (const float*)d_in[3];
    const float* b1    = (const float*)d_in[4];
    const float* W2    = (const float*)d_in[5];
    const float* b2    = (const float*)d_in[6];
    const float* W_out = (const float*)d_in[7];
    const float* b_out = (const float*)d_in[8];

    size_t smem = (size_t)(2 * LATD + HIDD) * SROW * sizeof(float);  // 80 KB

    static bool attr_done = false;
    if (!attr_done) {
        cudaFuncSetAttribute(ode_kernel, cudaFuncAttributeMaxDynamicSharedMemorySize, (int)smem);
        attr_done = true;
    }

    ode_kernel<<<NCTA, BDIM, smem>>>(x, W_in, b_in, W1, b1, W2, b2, W_out, b_out,
                                     (float*)d_out);
}

// round 7
// speedup vs baseline: 2.1870x; 1.3535x over previous
#include <cuda_runtime.h>
#include <cuda_bf16.h>
#include <cstdint>

#define NCTA  128
#define BDIM  256
#define LATD  512
#define HIDD  1024
#define NSTEPS 20

// ---------------- persistent device state ----------------
__device__ __align__(16) __nv_bfloat16 g_w1t_hi[HIDD * LATD];   // W1^T [n=1024][k=512]
__device__ __align__(16) __nv_bfloat16 g_w1t_lo[HIDD * LATD];
__device__ __align__(16) __nv_bfloat16 g_w2t_hi[LATD * HIDD];   // W2^T [n=512][k=1024]
__device__ __align__(16) __nv_bfloat16 g_w2t_lo[LATD * HIDD];
__device__ __align__(16) __nv_bfloat16 g_src_hi[1024 * LATD];   // GEMM1 A [m][k]
__device__ __align__(16) __nv_bfloat16 g_src_lo[1024 * LATD];
__device__ __align__(16) __nv_bfloat16 g_act_hi[1024 * HIDD];   // GEMM2 A [m][k]
__device__ __align__(16) __nv_bfloat16 g_act_lo[1024 * HIDD];
__device__ float         g_h [1024 * LATD];                     // fp32 master state
__device__ float         g_rk[1024 * LATD];                     // RK4 accumulator
__device__ unsigned int  g_ctr = 0;
__device__ unsigned int  g_seq = 0;

// ---------------- helpers ----------------
__device__ __forceinline__ uint32_t smem_u32(const void* p) {
    uint32_t a;
    asm("{ .reg .u64 t; cvta.to.shared.u64 t, %1; cvt.u32.u64 %0, t; }" : "=r"(a) : "l"(p));
    return a;
}
__device__ __forceinline__ void mma_bf16(float* c, const unsigned* a, unsigned b0, unsigned b1) {
    asm volatile(
        "mma.sync.aligned.m16n8k16.row.col.f32.bf16.bf16.f32 "
        "{%0,%1,%2,%3}, {%4,%5,%6,%7}, {%8,%9}, {%0,%1,%2,%3};"
        : "+f"(c[0]), "+f"(c[1]), "+f"(c[2]), "+f"(c[3])
        : "r"(a[0]), "r"(a[1]), "r"(a[2]), "r"(a[3]), "r"(b0), "r"(b1));
}
__device__ __forceinline__ float fast_tanh(float x) {
    float e = __expf(2.0f * x);
    return 1.0f - __fdividef(2.0f, e + 1.0f);
}
__device__ __forceinline__ unsigned pack_bf(float a, float b) {
    return (unsigned)__bfloat16_as_ushort(__float2bfloat16(a)) |
           ((unsigned)__bfloat16_as_ushort(__float2bfloat16(b)) << 16);
}
typedef unsigned long long ull;
__device__ __forceinline__ ull pack2(float v) {
    ull r; asm("mov.b64 %0, {%1, %1};" : "=l"(r) : "r"(__float_as_uint(v))); return r;
}
__device__ __forceinline__ void ffma2(ull &d, ull a, ull b) {
    asm("fma.rn.f32x2 %0, %1, %2, %0;" : "+l"(d) : "l"(a), "l"(b));
}
__device__ __forceinline__ void unpack2(ull v, float &lo, float &hi) {
    unsigned a, b; asm("mov.b64 {%0, %1}, %2;" : "=r"(a), "=r"(b) : "l"(v));
    lo = __uint_as_float(a); hi = __uint_as_float(b);
}

// grid barrier: monotonic seq; ctr reset by last arriver before fenced seq bump.
__device__ __forceinline__ void gridbar(unsigned target) {
    __threadfence();
    __syncthreads();
    if (threadIdx.x == 0) {
        unsigned p = atomicAdd(&g_ctr, 1);
        if (p == NCTA - 1) {
            g_ctr = 0;
            __threadfence();
            atomicAdd(&g_seq, 1);
        } else {
            while (*(volatile unsigned*)&g_seq < target) { __nanosleep(32); }
        }
        __threadfence();
    }
    __syncthreads();
}

// ---------------- cooperative GEMM on mma.sync ----------------
// SMEM buffer (55296 B each, 2 buffers):
//   A_hi[128x64] rows padded to 144B : off 0      (18432 B)
//   A_lo                             : off 18432
//   B_hi[NBx64]                      : off 36864  (<= 9216 B)
//   B_lo                             : off 46080
// Row stride 144 B = 36 words -> bank = (4g+w) mod 32, conflict-free frags.
template<int NF, int NCH>
__device__ __forceinline__ void gemm_tc(
    unsigned char* dyn, uint32_t sdyn,
    const __nv_bfloat16* __restrict__ Agh, const __nv_bfloat16* __restrict__ Agl, int ldA, int m0,
    const __nv_bfloat16* __restrict__ Bgh, const __nv_bfloat16* __restrict__ Bgl, int ldB, int n0,
    float C[2][4][4])
{
    const int tid = threadIdx.x;
    const int NB = NF * 16;            // B tile rows (64 or 32)
    const int totA = 2048, totB = NB * 16;

    #pragma unroll
    for (int f = 0; f < 2; f++)
        #pragma unroll
        for (int nf = 0; nf < NF; nf++)
            #pragma unroll
            for (int c = 0; c < 4; c++) C[f][nf][c] = 0.0f;

    const int lane = tid & 31, wrp = tid >> 5;
    const int wm = wrp >> 1, wn = wrp & 1;
    const int g = lane >> 2, ws = lane & 3;

    // prefetch chunk 0
    {
        uint32_t sb = sdyn;
        for (int i = tid; i < totA + totB; i += BDIM) {
            const __nv_bfloat16* gp; uint32_t sp;
            if (i < totA) {
                int half = i >> 10, j = i & 1023;
                int r = j >> 3, c = j & 7;
                gp = (half ? Agl : Agh) + (size_t)(m0 + r) * ldA + c * 8;
                sp = sb + half * 18432 + r * 144 + c * 16;
            } else {
                int j = i - totA;
                int half = j >= NB * 8;
                int jj = half ? j - NB * 8 : j;
                int r = jj >> 3, c = jj & 7;
                gp = (half ? Bgl : Bgh) + (size_t)(n0 + r) * ldB + c * 8;
                sp = sb + 36864 + half * 9216 + r * 144 + c * 16;
            }
            asm volatile("cp.async.cg.shared.global [%0], [%1], 16;" :: "r"(sp), "l"(gp));
        }
        asm volatile("cp.async.commit_group;" ::: "memory");
    }

    for (int kc = 0; kc < NCH; kc++) {
        if (kc + 1 < NCH) {
            int k0 = (kc + 1) * 64;
            uint32_t sb = sdyn + ((kc + 1) & 1) * 55296;
            for (int i = tid; i < totA + totB; i += BDIM) {
                const __nv_bfloat16* gp; uint32_t sp;
                if (i < totA) {
                    int half = i >> 10, j = i & 1023;
                    int r = j >> 3, c = j & 7;
                    gp = (half ? Agl : Agh) + (size_t)(m0 + r) * ldA + k0 + c * 8;
                    sp = sb + half * 18432 + r * 144 + c * 16;
                } else {
                    int j = i - totA;
                    int half = j >= NB * 8;
                    int jj = half ? j - NB * 8 : j;
                    int r = jj >> 3, c = jj & 7;
                    gp = (half ? Bgl : Bgh) + (size_t)(n0 + r) * ldB + k0 + c * 8;
                    sp = sb + 36864 + half * 9216 + r * 144 + c * 16;
                }
                asm volatile("cp.async.cg.shared.global [%0], [%1], 16;" :: "r"(sp), "l"(gp));
            }
            asm volatile("cp.async.commit_group;" ::: "memory");
            asm volatile("cp.async.wait_group 1;" ::: "memory");
        } else {
            asm volatile("cp.async.wait_group 0;" ::: "memory");
        }
        __syncthreads();

        unsigned char* bb = dyn + (kc & 1) * 55296;
        const unsigned* Ah = (const unsigned*)(bb);
        const unsigned* Al = (const unsigned*)(bb + 18432);
        const unsigned* Bh = (const unsigned*)(bb + 36864);
        const unsigned* Bl = (const unsigned*)(bb + 46080);

        #pragma unroll
        for (int ks = 0; ks < 4; ks++) {
            int kw = ks * 8 + ws;
            unsigned ah[2][4], al[2][4];
            #pragma unroll
            for (int f = 0; f < 2; f++) {
                int r0 = (wm * 32 + f * 16 + g) * 36 + kw;
                int r1 = r0 + 8 * 36;
                ah[f][0] = Ah[r0];     ah[f][1] = Ah[r1];
                ah[f][2] = Ah[r0 + 4]; ah[f][3] = Ah[r1 + 4];
                al[f][0] = Al[r0];     al[f][1] = Al[r1];
                al[f][2] = Al[r0 + 4]; al[f][3] = Al[r1 + 4];
            }
            #pragma unroll
            for (int nf = 0; nf < NF; nf++) {
                int rn = (wn * NF * 8 + nf * 8 + g) * 36 + kw;
                unsigned bh0 = Bh[rn], bh1 = Bh[rn + 4];
                unsigned bl0 = Bl[rn], bl1 = Bl[rn + 4];
                #pragma unroll
                for (int f = 0; f < 2; f++) {
                    mma_bf16(C[f][nf], ah[f], bh0, bh1);   // hi*hi
                    mma_bf16(C[f][nf], ah[f], bl0, bl1);   // hi*lo
                    mma_bf16(C[f][nf], al[f], bh0, bh1);   // lo*hi
                }
            }
        }
        __syncthreads();
    }
}

// ---------------- the persistent kernel ----------------
extern "C" __global__ void __launch_bounds__(BDIM, 1)
ode_tc(const float* __restrict__ x,     const float* __restrict__ W_in,
       const float* __restrict__ b_in,  const float* __restrict__ W1,
       const float* __restrict__ b1,    const float* __restrict__ W2,
       const float* __restrict__ b2,    const float* __restrict__ W_out,
       const float* __restrict__ b_out, float* __restrict__ out)
{
    extern __shared__ __align__(1024) unsigned char dyn[];
    __shared__ float sb1[64], sw1r[64], sb2[32];

    const int tid  = threadIdx.x;
    const int lane = tid & 31, wrp = tid >> 5;
    const int wm = wrp >> 1, wn = wrp & 1;
    const int g = lane >> 2, ws = lane & 3;
    const int bid = blockIdx.x;
    const int mt  = bid >> 4, nt = bid & 15;
    const int m0  = mt * 128, n0 = nt * 64, j0 = nt * 32;
    const uint32_t sdyn = smem_u32(dyn);

    unsigned base_seq = *(volatile unsigned*)&g_seq;   // stable between launches
    unsigned nbar = 0;

    if (tid < 64) {
        sb1[tid]  = b1[n0 + tid];
        sw1r[tid] = W1[(size_t)LATD * HIDD + n0 + tid];   // t-row of W1
    }
    if (tid < 32) sb2[tid] = b2[j0 + tid];

    // ---- prepass: split+transpose weights to bf16 hi/lo ----
    for (int idx = bid * BDIM + tid; idx < HIDD * LATD; idx += NCTA * BDIM) {
        int n = idx & 1023, k = idx >> 10;
        float v = W1[(size_t)k * HIDD + n];
        __nv_bfloat16 h = __float2bfloat16(v);
        g_w1t_hi[n * LATD + k] = h;
        g_w1t_lo[n * LATD + k] = __float2bfloat16(v - __bfloat162float(h));
    }
    for (int idx = bid * BDIM + tid; idx < LATD * HIDD; idx += NCTA * BDIM) {
        int n = idx & 511, k = idx >> 9;
        float v = W2[(size_t)k * LATD + n];
        __nv_bfloat16 h = __float2bfloat16(v);
        g_w2t_hi[n * HIDD + k] = h;
        g_w2t_lo[n * HIDD + k] = __float2bfloat16(v - __bfloat162float(h));
    }

    // ---- h0 = tanh(x @ W_in + b_in) for this CTA's 8 rows (fp32 SIMT) ----
    {
        float* xT = (float*)dyn;                       // [256][10]
        int r0 = bid * 8;
        for (int i = tid; i < 2048; i += BDIM) {
            int f = i & 255, rr = i >> 8;
            xT[f * 10 + rr] = x[(size_t)(r0 + rr) * 256 + f];
        }
        __syncthreads();
        int jj = tid * 2;
        ull acc[4][2];
        #pragma unroll
        for (int p = 0; p < 4; p++) { acc[p][0] = 0ull; acc[p][1] = 0ull; }
        #pragma unroll 4
        for (int k = 0; k < 256; k++) {
            float2 w = *(const float2*)(W_in + (size_t)k * LATD + jj);
            ull w0 = pack2(w.x), w1 = pack2(w.y);
            #pragma unroll
            for (int p = 0; p < 4; p++) {
                ull a = *(const ull*)(xT + k * 10 + 2 * p);
                ffma2(acc[p][0], a, w0);
                ffma2(acc[p][1], a, w1);
            }
        }
        float bv0 = b_in[jj], bv1 = b_in[jj + 1];
        #pragma unroll
        for (int p = 0; p < 4; p++) {
            float lo0, hi0, lo1, hi1;
            unpack2(acc[p][0], lo0, hi0);
            unpack2(acc[p][1], lo1, hi1);
            float v[2][2] = { { fast_tanh(lo0 + bv0), fast_tanh(hi0 + bv0) },
                              { fast_tanh(lo1 + bv1), fast_tanh(hi1 + bv1) } };
            #pragma unroll
            for (int q = 0; q < 2; q++) {
                int m = r0 + 2 * p + q;
                #pragma unroll
                for (int c = 0; c < 2; c++) {
                    float val = v[c][q];
                    g_h[(size_t)m * LATD + jj + c] = val;
                    __nv_bfloat16 hb = __float2bfloat16(val);
                    g_src_hi[(size_t)m * LATD + jj + c] = hb;
                    g_src_lo[(size_t)m * LATD + jj + c] =
                        __float2bfloat16(val - __bfloat162float(hb));
                }
            }
        }
        __syncthreads();
    }
    gridbar(base_seq + (++nbar));

    const float dt = 1.0f / NSTEPS;
    float C[2][4][4];

    for (int step = 0; step < NSTEPS; step++) {
        float t = dt * step;
        #pragma unroll 1
        for (int stage = 0; stage < 4; stage++) {
            float ts = t + ((stage == 0) ? 0.0f : (stage == 3) ? dt : 0.5f * dt);

            // ==== GEMM1: z = src @ W1  (tile 128x64, K=512, 8 chunks) ====
            gemm_tc<4, 8>(dyn, sdyn, g_src_hi, g_src_lo, LATD, m0,
                          g_w1t_hi, g_w1t_lo, LATD, n0, C);
            #pragma unroll
            for (int f = 0; f < 2; f++)
                #pragma unroll
                for (int nf = 0; nf < 4; nf++) {
                    int nl = wn * 32 + nf * 8 + 2 * ws;
                    float bb0 = sb1[nl]     + ts * sw1r[nl];
                    float bb1 = sb1[nl + 1] + ts * sw1r[nl + 1];
                    #pragma unroll
                    for (int hr = 0; hr < 2; hr++) {
                        float a0 = fast_tanh(C[f][nf][hr * 2]     + bb0);
                        float a1 = fast_tanh(C[f][nf][hr * 2 + 1] + bb1);
                        int m = m0 + wm * 32 + f * 16 + g + hr * 8;
                        size_t w = ((size_t)m * HIDD + n0 + nl) >> 1;
                        float r0 = __bfloat162float(__float2bfloat16(a0));
                        float r1 = __bfloat162float(__float2bfloat16(a1));
                        ((unsigned*)g_act_hi)[w] = pack_bf(a0, a1);
                        ((unsigned*)g_act_lo)[w] = pack_bf(a0 - r0, a1 - r1);
                    }
                }
            gridbar(base_seq + (++nbar));

            // ==== GEMM2: k = act @ W2  (tile 128x32, K=1024, 16 chunks) ====
            gemm_tc<2, 16>(dyn, sdyn, g_act_hi, g_act_lo, HIDD, m0,
                           g_w2t_hi, g_w2t_lo, HIDD, j0, C);
            #pragma unroll
            for (int f = 0; f < 2; f++)
                #pragma unroll
                for (int nf = 0; nf < 2; nf++) {
                    int nl = wn * 16 + nf * 8 + 2 * ws;
                    #pragma unroll
                    for (int hr = 0; hr < 2; hr++) {
                        int m = m0 + wm * 32 + f * 16 + g + hr * 8;
                        float kk0 = C[f][nf][hr * 2]     + sb2[nl];
                        float kk1 = C[f][nf][hr * 2 + 1] + sb2[nl + 1];
                        float* hp = g_h  + (size_t)m * LATD + j0 + nl;
                        float* rp = g_rk + (size_t)m * LATD + j0 + nl;
                        float2 hv = *(const float2*)hp;
                        float sv0, sv1;
                        if (stage == 0) {
                            float2 rv; rv.x = kk0; rv.y = kk1;
                            *(float2*)rp = rv;
                            sv0 = hv.x + 0.5f * dt * kk0; sv1 = hv.y + 0.5f * dt * kk1;
                        } else if (stage == 1) {
                            float2 rv = *(const float2*)rp;
                            rv.x += 2.0f * kk0; rv.y += 2.0f * kk1;
                            *(float2*)rp = rv;
                            sv0 = hv.x + 0.5f * dt * kk0; sv1 = hv.y + 0.5f * dt * kk1;
                        } else if (stage == 2) {
                            float2 rv = *(const float2*)rp;
                            rv.x += 2.0f * kk0; rv.y += 2.0f * kk1;
                            *(float2*)rp = rv;
                            sv0 = hv.x + dt * kk0; sv1 = hv.y + dt * kk1;
                        } else {
                            float2 rv = *(const float2*)rp;
                            sv0 = hv.x + (dt / 6.0f) * (rv.x + kk0);
                            sv1 = hv.y + (dt / 6.0f) * (rv.y + kk1);
                            float2 nh; nh.x = sv0; nh.y = sv1;
                            *(float2*)hp = nh;
                        }
                        size_t w = ((size_t)m * LATD + j0 + nl) >> 1;
                        float r0 = __bfloat162float(__float2bfloat16(sv0));
                        float r1 = __bfloat162float(__float2bfloat16(sv1));
                        ((unsigned*)g_src_hi)[w] = pack_bf(sv0, sv1);
                        ((unsigned*)g_src_lo)[w] = pack_bf(sv0 - r0, sv1 - r1);
                    }
                }
            gridbar(base_seq + (++nbar));
        }
    }

    // ---- out = h[:, :256] @ W_out + b_out for this CTA's 8 rows ----
    {
        float* sh = (float*)dyn;               // [8][256]
        int r0 = bid * 8;
        for (int i = tid; i < 2048; i += BDIM) {
            int f = i & 255, rr = i >> 8;
            sh[rr * 256 + f] = g_h[(size_t)(r0 + rr) * LATD + f];
        }
        __syncthreads();
        int m = tid >> 5, o0 = (tid & 31) * 2;
        float s0 = 0.0f, s1 = 0.0f;
        #pragma unroll 4
        for (int k = 0; k < 256; k++) {
            float hv = sh[m * 256 + k];
            float2 w = *(const float2*)(W_out + (size_t)k * 64 + o0);
            s0 = fmaf(hv, w.x, s0);
            s1 = fmaf(hv, w.y, s1);
        }
        float2 o;
        o.x = s0 + b_out[o0];
        o.y = s1 + b_out[o0 + 1];
        *(float2*)(out + (size_t)(r0 + m) * 64 + o0) = o;
    }
}

extern "C" void kernel_launch(void* const* d_in, const int* in_sizes, int n_in,
                              void* d_out, int out_size)
{
    const float* x     = (const float*)d_in[0];
    const float* W_in  = (const float*)d_in[1];
    const float* b_in  = (const float*)d_in[2];
    const float* W1    = (const float*)d_in[3];
    const float* b1    = (const float*)d_in[4];
    const float* W2    = (const float*)d_in[5];
    const float* b2    = (const float*)d_in[6];
    const float* W_out = (const float*)d_in[7];
    const float* b_out = (const float*)d_in[8];

    const size_t smem = 2 * 55296;   // two double-buffered chunk buffers (108 KB)
    static bool attr_done = false;
    if (!attr_done) {
        cudaFuncSetAttribute(ode_tc, cudaFuncAttributeMaxDynamicSharedMemorySize, (int)smem);
        attr_done = true;
    }
    ode_tc<<<NCTA, BDIM, smem>>>(x, W_in, b_in, W1, b1, W2, b2, W_out, b_out,
                                 (float*)d_out);
}